// round 1
// baseline (speedup 1.0000x reference)
#include <cuda_runtime.h>
#include <math_constants.h>

// Problem constants
#define B_DIM 64
#define J_DIM 17
#define HW_DIM 9216
#define BJ (B_DIM * J_DIM)
#define TOPK 8

// Scratch (device globals — no allocation allowed)
__device__ float g_sum_sg[BJ];
__device__ float g_sum_st[BJ];
__device__ float g_max_g[BJ];

__inline__ __device__ float warpReduceSum(float v) {
    #pragma unroll
    for (int o = 16; o > 0; o >>= 1) v += __shfl_down_sync(0xffffffffu, v, o);
    return v;
}
__inline__ __device__ float warpReduceMax(float v) {
    #pragma unroll
    for (int o = 16; o > 0; o >>= 1) v = fmaxf(v, __shfl_down_sync(0xffffffffu, v, o));
    return v;
}

// Kernel 1: one block per (b,j) plane. Reduce sum((s-g)^2), sum((s-t)^2), max(g).
__global__ __launch_bounds__(256) void reduce_planes_kernel(
    const float* __restrict__ s_in,
    const float* __restrict__ t_in,
    const float* __restrict__ g_in)
{
    const int bj = blockIdx.x;
    const int tid = threadIdx.x;

    const float4* s4 = reinterpret_cast<const float4*>(s_in) + (size_t)bj * (HW_DIM / 4);
    const float4* t4 = reinterpret_cast<const float4*>(t_in) + (size_t)bj * (HW_DIM / 4);
    const float4* g4 = reinterpret_cast<const float4*>(g_in) + (size_t)bj * (HW_DIM / 4);

    float ssg = 0.0f, sst = 0.0f, mg = -CUDART_INF_F;

    // HW/4 = 2304 float4s, 256 threads -> 9 iterations
    #pragma unroll 3
    for (int i = tid; i < HW_DIM / 4; i += 256) {
        float4 a = s4[i];
        float4 b = t4[i];
        float4 c = g4[i];
        float d;
        d = a.x - c.x; ssg = fmaf(d, d, ssg);
        d = a.y - c.y; ssg = fmaf(d, d, ssg);
        d = a.z - c.z; ssg = fmaf(d, d, ssg);
        d = a.w - c.w; ssg = fmaf(d, d, ssg);
        d = a.x - b.x; sst = fmaf(d, d, sst);
        d = a.y - b.y; sst = fmaf(d, d, sst);
        d = a.z - b.z; sst = fmaf(d, d, sst);
        d = a.w - b.w; sst = fmaf(d, d, sst);
        mg = fmaxf(mg, fmaxf(fmaxf(c.x, c.y), fmaxf(c.z, c.w)));
    }

    // block reduction (8 warps)
    __shared__ float sh_sg[8], sh_st[8], sh_mg[8];
    ssg = warpReduceSum(ssg);
    sst = warpReduceSum(sst);
    mg  = warpReduceMax(mg);
    const int lane = tid & 31, wid = tid >> 5;
    if (lane == 0) { sh_sg[wid] = ssg; sh_st[wid] = sst; sh_mg[wid] = mg; }
    __syncthreads();
    if (wid == 0) {
        ssg = (lane < 8) ? sh_sg[lane] : 0.0f;
        sst = (lane < 8) ? sh_st[lane] : 0.0f;
        mg  = (lane < 8) ? sh_mg[lane] : -CUDART_INF_F;
        ssg = warpReduceSum(ssg);
        sst = warpReduceSum(sst);
        mg  = warpReduceMax(mg);
        if (lane == 0) {
            g_sum_sg[bj] = ssg;
            g_sum_st[bj] = sst;
            g_max_g[bj]  = mg;
        }
    }
}

// Kernel 2: single block. cond per joint, per-(b,j) loss, top-8 of 17 per b,
// final reduction -> 3 output scalars.
__global__ __launch_bounds__(128) void finalize_kernel(
    const float* __restrict__ w_in,   // [B, J] (target_weight, trailing dim 1)
    const int*  __restrict__ enj_in,  // effective_num_joints
    float* __restrict__ out)
{
    const int tid = threadIdx.x;
    __shared__ float cond_sh[J_DIM];       // 1.0 if cond else 0.0
    __shared__ float topk_sh[B_DIM];
    __shared__ float all_sh[B_DIM];

    if (tid < J_DIM) {
        float m = -CUDART_INF_F;
        #pragma unroll
        for (int b = 0; b < B_DIM; b++) m = fmaxf(m, g_max_g[b * J_DIM + tid]);
        cond_sh[tid] = (m == 1.0f) ? 1.0f : 0.0f;
    }
    __syncthreads();

    if (tid < B_DIM) {
        float lm[J_DIM];
        float sum_all = 0.0f;
        #pragma unroll
        for (int j = 0; j < J_DIM; j++) {
            const int idx = tid * J_DIM + j;
            const float wv = w_in[idx];
            float v = g_sum_sg[idx];
            if (cond_sh[j] == 0.0f) v += g_sum_st[idx];
            const float l = 0.5f * wv * wv * v * (1.0f / (float)HW_DIM);
            lm[j] = l;
            sum_all += l;
        }
        // top-8 of 17 by repeated selection
        float tk = 0.0f;
        #pragma unroll
        for (int k = 0; k < TOPK; k++) {
            float bv = -CUDART_INF_F;
            int bi = 0;
            #pragma unroll
            for (int j = 0; j < J_DIM; j++) {
                if (lm[j] > bv) { bv = lm[j]; bi = j; }
            }
            tk += bv;
            lm[bi] = -CUDART_INF_F;
        }
        topk_sh[tid] = tk * (1.0f / (float)TOPK);
        all_sh[tid]  = sum_all;
    }
    __syncthreads();

    if (tid == 0) {
        float ohkm = 0.0f, all = 0.0f;
        #pragma unroll
        for (int b = 0; b < B_DIM; b++) { ohkm += topk_sh[b]; all += all_sh[b]; }
        ohkm *= (1.0f / (float)B_DIM);
        // mse = sum_j where(cond, m_sg, m_sg+m_st)  ==  (2/B) * sum_{b,j} loss_mat
        const float mse = all * (2.0f / (float)B_DIM);
        const float enj = (float)(*enj_in);
        out[0] = ohkm;
        out[1] = mse / enj;
        out[2] = ohkm + mse;
    }
}

extern "C" void kernel_launch(void* const* d_in, const int* in_sizes, int n_in,
                              void* d_out, int out_size) {
    const float* output_s = (const float*)d_in[0];
    const float* output_t = (const float*)d_in[1];
    const float* target   = (const float*)d_in[2];
    const float* tweight  = (const float*)d_in[3];
    const int*   enj      = (const int*)d_in[4];
    float* out = (float*)d_out;

    reduce_planes_kernel<<<BJ, 256>>>(output_s, output_t, target);
    finalize_kernel<<<1, 128>>>(tweight, enj, out);
}

// round 2
// speedup vs baseline: 1.0167x; 1.0167x over previous
#include <cuda_runtime.h>
#include <math_constants.h>

// Problem constants
#define B_DIM 64
#define J_DIM 17
#define HW_DIM 9216
#define BJ (B_DIM * J_DIM)
#define TOPK 8
#define NTHREADS 256

// Scratch (device globals — no allocation allowed)
__device__ float g_sum_sg[BJ];
__device__ float g_sum_st[BJ];
__device__ float g_max_g[BJ];
__device__ unsigned int g_counter = 0;   // reset by last block each run

__inline__ __device__ float warpReduceSum(float v) {
    #pragma unroll
    for (int o = 16; o > 0; o >>= 1) v += __shfl_down_sync(0xffffffffu, v, o);
    return v;
}
__inline__ __device__ float warpReduceMax(float v) {
    #pragma unroll
    for (int o = 16; o > 0; o >>= 1) v = fmaxf(v, __shfl_down_sync(0xffffffffu, v, o));
    return v;
}

// One block per (b,j) plane: reduce sum((s-g)^2), sum((s-t)^2), max(g).
// The last block to finish also performs the finalization.
__global__ __launch_bounds__(NTHREADS) void fused_loss_kernel(
    const float* __restrict__ s_in,
    const float* __restrict__ t_in,
    const float* __restrict__ g_in,
    const float* __restrict__ w_in,   // [B*J]
    const int*  __restrict__ enj_in,
    float* __restrict__ out)
{
    const int bj = blockIdx.x;
    const int tid = threadIdx.x;

    const float4* s4 = reinterpret_cast<const float4*>(s_in) + (size_t)bj * (HW_DIM / 4);
    const float4* t4 = reinterpret_cast<const float4*>(t_in) + (size_t)bj * (HW_DIM / 4);
    const float4* g4 = reinterpret_cast<const float4*>(g_in) + (size_t)bj * (HW_DIM / 4);

    float ssg = 0.0f, sst = 0.0f, mg = -CUDART_INF_F;

    // HW/4 = 2304 float4s, 256 threads -> 9 iterations
    #pragma unroll 3
    for (int i = tid; i < HW_DIM / 4; i += NTHREADS) {
        float4 a = s4[i];
        float4 b = t4[i];
        float4 c = g4[i];
        float d;
        d = a.x - c.x; ssg = fmaf(d, d, ssg);
        d = a.y - c.y; ssg = fmaf(d, d, ssg);
        d = a.z - c.z; ssg = fmaf(d, d, ssg);
        d = a.w - c.w; ssg = fmaf(d, d, ssg);
        d = a.x - b.x; sst = fmaf(d, d, sst);
        d = a.y - b.y; sst = fmaf(d, d, sst);
        d = a.z - b.z; sst = fmaf(d, d, sst);
        d = a.w - b.w; sst = fmaf(d, d, sst);
        mg = fmaxf(mg, fmaxf(fmaxf(c.x, c.y), fmaxf(c.z, c.w)));
    }

    // Block reduction (8 warps)
    __shared__ float sh_sg[8], sh_st[8], sh_mg[8];
    ssg = warpReduceSum(ssg);
    sst = warpReduceSum(sst);
    mg  = warpReduceMax(mg);
    const int lane = tid & 31, wid = tid >> 5;
    if (lane == 0) { sh_sg[wid] = ssg; sh_st[wid] = sst; sh_mg[wid] = mg; }
    __syncthreads();

    __shared__ unsigned int is_last;
    if (wid == 0) {
        ssg = (lane < 8) ? sh_sg[lane] : 0.0f;
        sst = (lane < 8) ? sh_st[lane] : 0.0f;
        mg  = (lane < 8) ? sh_mg[lane] : -CUDART_INF_F;
        ssg = warpReduceSum(ssg);
        sst = warpReduceSum(sst);
        mg  = warpReduceMax(mg);
        if (lane == 0) {
            g_sum_sg[bj] = ssg;
            g_sum_st[bj] = sst;
            g_max_g[bj]  = mg;
            __threadfence();
            unsigned int prev = atomicAdd(&g_counter, 1u);
            is_last = (prev == BJ - 1) ? 1u : 0u;
        }
    }
    __syncthreads();
    if (is_last == 0u) return;

    // ---------------- Finalization (last block only, 256 threads) ----------------
    __shared__ float f_sg[BJ];
    __shared__ float f_st[BJ];
    __shared__ float f_mx[BJ];
    __shared__ float f_w[BJ];
    __shared__ float cond_sh[J_DIM];   // 1.0 if cond else 0.0
    __shared__ float topk_sh[B_DIM];
    __shared__ float all_sh[B_DIM];

    // Cooperative load of all scratch + weights (independent L2 loads)
    #pragma unroll
    for (int i = tid; i < BJ; i += NTHREADS) {
        f_sg[i] = g_sum_sg[i];
        f_st[i] = g_sum_st[i];
        f_mx[i] = g_max_g[i];
        f_w[i]  = w_in[i];
    }
    __syncthreads();

    if (tid < J_DIM) {
        float m = -CUDART_INF_F;
        #pragma unroll
        for (int b = 0; b < B_DIM; b++) m = fmaxf(m, f_mx[b * J_DIM + tid]);
        cond_sh[tid] = (m == 1.0f) ? 1.0f : 0.0f;
    }
    __syncthreads();

    if (tid < B_DIM) {
        float lm[J_DIM];
        float sum_all = 0.0f;
        #pragma unroll
        for (int j = 0; j < J_DIM; j++) {
            const int idx = tid * J_DIM + j;
            const float wv = f_w[idx];
            float v = f_sg[idx];
            if (cond_sh[j] == 0.0f) v += f_st[idx];
            const float l = 0.5f * wv * wv * v * (1.0f / (float)HW_DIM);
            lm[j] = l;
            sum_all += l;
        }
        // top-8 of 17 by repeated selection
        float tk = 0.0f;
        #pragma unroll
        for (int k = 0; k < TOPK; k++) {
            float bv = -CUDART_INF_F;
            int bi = 0;
            #pragma unroll
            for (int j = 0; j < J_DIM; j++) {
                if (lm[j] > bv) { bv = lm[j]; bi = j; }
            }
            tk += bv;
            lm[bi] = -CUDART_INF_F;
        }
        topk_sh[tid] = tk * (1.0f / (float)TOPK);
        all_sh[tid]  = sum_all;
    }
    __syncthreads();

    if (tid == 0) {
        float ohkm = 0.0f, all = 0.0f;
        #pragma unroll
        for (int b = 0; b < B_DIM; b++) { ohkm += topk_sh[b]; all += all_sh[b]; }
        ohkm *= (1.0f / (float)B_DIM);
        // mse = sum_j where(cond, m_sg, m_sg+m_st)  ==  (2/B) * sum_{b,j} loss_mat
        const float mse = all * (2.0f / (float)B_DIM);
        const float enj = (float)(*enj_in);
        out[0] = ohkm;
        out[1] = mse / enj;
        out[2] = ohkm + mse;
        g_counter = 0u;   // reset for next graph replay
    }
}

extern "C" void kernel_launch(void* const* d_in, const int* in_sizes, int n_in,
                              void* d_out, int out_size) {
    const float* output_s = (const float*)d_in[0];
    const float* output_t = (const float*)d_in[1];
    const float* target   = (const float*)d_in[2];
    const float* tweight  = (const float*)d_in[3];
    const int*   enj      = (const int*)d_in[4];
    float* out = (float*)d_out;

    fused_loss_kernel<<<BJ, NTHREADS>>>(output_s, output_t, target, tweight, enj, out);
}